// round 2
// baseline (speedup 1.0000x reference)
#include <cuda_runtime.h>
#include <cuda_bf16.h>
#include <math_constants.h>

#define DIM 1024
#define NHEADS 16
#define HDIM 64
#define B 2
#define S 2048
#define M_TOT (B * S)            // 4096
#define EPS 1e-6f

// ---------------- scratch (static device globals; no allocation) ----------------
__device__ float g_qkv[(size_t)M_TOT * 3 * DIM];           // [4096, 3072]
__device__ float g_q[(size_t)B * NHEADS * S * HDIM];       // [B,H,S,D]
__device__ float g_k[(size_t)B * NHEADS * S * HDIM];
__device__ float g_v[(size_t)B * NHEADS * S * HDIM];
__device__ float g_o[(size_t)M_TOT * DIM];                 // [4096, 1024] attn output

// ---------------- Kernel 1/4: SGEMM NT  C[m,n] = sum_k A[m,k]*Bm[n,k] (+bias) ----
// A: [M,K] row-major, Bm: [N,K] row-major. 128x128 tile, BK=8, 256 threads, 8x8/thread.
__global__ void __launch_bounds__(256) sgemm_nt(const float* __restrict__ A,
                                                const float* __restrict__ Bm,
                                                const float* __restrict__ bias,
                                                float* __restrict__ C,
                                                int M, int N, int K) {
    __shared__ float As[8][128];
    __shared__ float Bs[8][128];

    const int bn = blockIdx.x * 128;
    const int bm = blockIdx.y * 128;
    const int tid = threadIdx.x;
    const int tx = tid & 15;   // n dir
    const int ty = tid >> 4;   // m dir

    const int lr = tid >> 1;        // 0..127 (row within tile)
    const int lc = (tid & 1) * 4;   // 0 or 4 (k offset)

    const float* Ab = A + (size_t)(bm + lr) * K + lc;
    const float* Bb = Bm + (size_t)(bn + lr) * K + lc;

    float acc[8][8];
#pragma unroll
    for (int i = 0; i < 8; i++)
#pragma unroll
        for (int j = 0; j < 8; j++) acc[i][j] = 0.f;

    for (int k0 = 0; k0 < K; k0 += 8) {
        float4 a4 = *(const float4*)(Ab + k0);
        float4 b4 = *(const float4*)(Bb + k0);
        __syncthreads();
        As[lc + 0][lr] = a4.x; As[lc + 1][lr] = a4.y;
        As[lc + 2][lr] = a4.z; As[lc + 3][lr] = a4.w;
        Bs[lc + 0][lr] = b4.x; Bs[lc + 1][lr] = b4.y;
        Bs[lc + 2][lr] = b4.z; Bs[lc + 3][lr] = b4.w;
        __syncthreads();
#pragma unroll
        for (int kk = 0; kk < 8; kk++) {
            float ar[8], br[8];
#pragma unroll
            for (int i = 0; i < 8; i++) {
                ar[i] = As[kk][ty * 8 + i];
                br[i] = Bs[kk][tx * 8 + i];
            }
#pragma unroll
            for (int i = 0; i < 8; i++)
#pragma unroll
                for (int j = 0; j < 8; j++) acc[i][j] = fmaf(ar[i], br[j], acc[i][j]);
        }
    }

#pragma unroll
    for (int i = 0; i < 8; i++) {
        const size_t mrow = (size_t)(bm + ty * 8 + i) * N + bn + tx * 8;
#pragma unroll
        for (int j4 = 0; j4 < 8; j4 += 4) {
            float4 o4;
            const int nc = bn + tx * 8 + j4;
            o4.x = acc[i][j4 + 0] + (bias ? bias[nc + 0] : 0.f);
            o4.y = acc[i][j4 + 1] + (bias ? bias[nc + 1] : 0.f);
            o4.z = acc[i][j4 + 2] + (bias ? bias[nc + 2] : 0.f);
            o4.w = acc[i][j4 + 3] + (bias ? bias[nc + 3] : 0.f);
            *(float4*)(C + mrow + j4) = o4;
        }
    }
}

// ---------------- Kernel 2/4: per-head LayerNorm + RoPE + scale + transpose ------
// grid: (B*S, H), block: 64. Reads qkv row [3][H][D]; writes Q,K,V in [B,H,S,D].
__global__ void __launch_bounds__(64) ln_rope_kernel(const float* __restrict__ qkv,
                                                     const float* __restrict__ qg,
                                                     const float* __restrict__ qb,
                                                     const float* __restrict__ kg,
                                                     const float* __restrict__ kb) {
    const int m = blockIdx.x;          // b*S + s
    const int h = blockIdx.y;
    const int d = threadIdx.x;         // 0..63
    const int b = m / S;
    const int s = m % S;

    const float* row = qkv + (size_t)m * (3 * DIM);
    float qv = row[h * HDIM + d];
    float kv = row[DIM + h * HDIM + d];
    float vv = row[2 * DIM + h * HDIM + d];

    __shared__ float r1[64], r2[64];
    __shared__ float qn[64], kn[64];

    // ---- Q layernorm ----
    r1[d] = qv; r2[d] = qv * qv;
    __syncthreads();
    for (int st = 32; st > 0; st >>= 1) {
        if (d < st) { r1[d] += r1[d + st]; r2[d] += r2[d + st]; }
        __syncthreads();
    }
    float mu = r1[0] * (1.f / HDIM);
    float var = r2[0] * (1.f / HDIM) - mu * mu;
    float qnv = (qv - mu) * rsqrtf(var + EPS) * qg[d] + qb[d];
    __syncthreads();

    // ---- K layernorm ----
    r1[d] = kv; r2[d] = kv * kv;
    __syncthreads();
    for (int st = 32; st > 0; st >>= 1) {
        if (d < st) { r1[d] += r1[d + st]; r2[d] += r2[d + st]; }
        __syncthreads();
    }
    mu = r1[0] * (1.f / HDIM);
    var = r2[0] * (1.f / HDIM) - mu * mu;
    float knv = (kv - mu) * rsqrtf(var + EPS) * kg[d] + kb[d];

    qn[d] = qnv; kn[d] = knv;
    __syncthreads();

    // ---- RoPE ----
    const int half = HDIM / 2;
    float fi = (float)(d & (half - 1)) / (float)half;
    float inv = powf(10000.f, -fi);
    float ang = (float)s * inv;
    float c, sn;
    sincosf(ang, &sn, &c);
    float qrot = (d < half) ? -qn[d + half] : qn[d - half];
    float krot = (d < half) ? -kn[d + half] : kn[d - half];
    float qo = (qnv * c + qrot * sn) * 0.125f;   // * D^-0.5
    float ko = knv * c + krot * sn;

    const size_t idx = (((size_t)(b * NHEADS + h)) * S + s) * HDIM + d;
    g_q[idx] = qo;
    g_k[idx] = ko;
    g_v[idx] = vv;
}

// ---------------- Kernel 3/4: flash attention, fp32 ------------------------------
// grid: (S/64, B*H), 256 threads (8 warps). Warp w owns q-rows w*8..w*8+7;
// lane j owns keys {j, j+32} in scores and out-dims {j, j+32} in PV.
#define BQ 64
#define BKT 64
#define KPAD 65
__global__ void __launch_bounds__(256) attn_kernel(const float* __restrict__ Q,
                                                   const float* __restrict__ K,
                                                   const float* __restrict__ V,
                                                   float* __restrict__ O) {
    extern __shared__ float sm[];
    float* Qs = sm;                    // 64*64
    float* Ks = Qs + BQ * HDIM;        // 64*65
    float* Vs = Ks + BKT * KPAD;       // 64*64
    float* Ps = Vs + BKT * HDIM;       // 64*64

    const int bh = blockIdx.y;         // b*H + h
    const int qt = blockIdx.x;
    const int b = bh / NHEADS;
    const int h = bh % NHEADS;

    const float* Qg = Q + ((size_t)bh * S + qt * BQ) * HDIM;
    const float* Kg = K + (size_t)bh * S * HDIM;
    const float* Vg = V + (size_t)bh * S * HDIM;

    const int tid = threadIdx.x;
    const int w = tid >> 5;
    const int j = tid & 31;
    const int r0 = w * 8;

    // load Q tile (4096 floats = 1024 float4)
#pragma unroll
    for (int i = 0; i < 4; i++) {
        int off = (tid + i * 256) * 4;
        *(float4*)(Qs + off) = *(const float4*)(Qg + off);
    }

    float mrow[8], lrow[8], acc0[8], acc1[8];
#pragma unroll
    for (int rr = 0; rr < 8; rr++) {
        mrow[rr] = -CUDART_INF_F; lrow[rr] = 0.f; acc0[rr] = 0.f; acc1[rr] = 0.f;
    }
    __syncthreads();

    for (int kt = 0; kt < S / BKT; kt++) {
        const float* Kt = Kg + (size_t)kt * BKT * HDIM;
        const float* Vt = Vg + (size_t)kt * BKT * HDIM;
#pragma unroll
        for (int i = 0; i < 4; i++) {
            int off = (tid + i * 256) * 4;
            int row = off >> 6, col = off & 63;
            float4 k4 = *(const float4*)(Kt + off);
            Ks[row * KPAD + col + 0] = k4.x;
            Ks[row * KPAD + col + 1] = k4.y;
            Ks[row * KPAD + col + 2] = k4.z;
            Ks[row * KPAD + col + 3] = k4.w;
            *(float4*)(Vs + off) = *(const float4*)(Vt + off);
        }
        __syncthreads();

        // scores: s0 = q . k[j], s1 = q . k[j+32]
        float s0[8], s1[8];
#pragma unroll
        for (int rr = 0; rr < 8; rr++) { s0[rr] = 0.f; s1[rr] = 0.f; }
        for (int kk = 0; kk < HDIM; kk++) {
            float k0 = Ks[j * KPAD + kk];
            float k1 = Ks[(j + 32) * KPAD + kk];
#pragma unroll
            for (int rr = 0; rr < 8; rr++) {
                float qv = Qs[(r0 + rr) * HDIM + kk];
                s0[rr] = fmaf(qv, k0, s0[rr]);
                s1[rr] = fmaf(qv, k1, s1[rr]);
            }
        }

        // online softmax per row
#pragma unroll
        for (int rr = 0; rr < 8; rr++) {
            float mx = fmaxf(s0[rr], s1[rr]);
#pragma unroll
            for (int off = 16; off; off >>= 1)
                mx = fmaxf(mx, __shfl_xor_sync(0xffffffffu, mx, off));
            float nm = fmaxf(mrow[rr], mx);
            float corr = expf(mrow[rr] - nm);
            float p0 = expf(s0[rr] - nm);
            float p1 = expf(s1[rr] - nm);
            float rs = p0 + p1;
#pragma unroll
            for (int off = 16; off; off >>= 1)
                rs += __shfl_xor_sync(0xffffffffu, rs, off);
            lrow[rr] = lrow[rr] * corr + rs;
            mrow[rr] = nm;
            acc0[rr] *= corr;
            acc1[rr] *= corr;
            Ps[(r0 + rr) * BKT + j] = p0;
            Ps[(r0 + rr) * BKT + j + 32] = p1;
        }
        __syncwarp();

        // PV: acc[rr][d in {j, j+32}] += sum_k P[rr][k] * V[k][d]
        for (int kk = 0; kk < BKT; kk++) {
            float v0 = Vs[kk * HDIM + j];
            float v1 = Vs[kk * HDIM + j + 32];
#pragma unroll
            for (int rr = 0; rr < 8; rr++) {
                float p = Ps[(r0 + rr) * BKT + kk];
                acc0[rr] = fmaf(p, v0, acc0[rr]);
                acc1[rr] = fmaf(p, v1, acc1[rr]);
            }
        }
        __syncthreads();
    }

    // write out to [B,S,C] with C index = h*64 + d
#pragma unroll
    for (int rr = 0; rr < 8; rr++) {
        float inv = 1.f / lrow[rr];
        size_t orow = ((size_t)b * S + qt * BQ + r0 + rr) * DIM + h * HDIM;
        O[orow + j] = acc0[rr] * inv;
        O[orow + j + 32] = acc1[rr] * inv;
    }
}

// ---------------- launch ---------------------------------------------------------
extern "C" void kernel_launch(void* const* d_in, const int* in_sizes, int n_in,
                              void* d_out, int out_size) {
    const float* x      = (const float*)d_in[0];
    const float* w_qkv  = (const float*)d_in[1];
    const float* w_proj = (const float*)d_in[2];
    const float* b_proj = (const float*)d_in[3];
    const float* q_g    = (const float*)d_in[4];
    const float* q_b    = (const float*)d_in[5];
    const float* k_g    = (const float*)d_in[6];
    const float* k_b    = (const float*)d_in[7];
    float* out = (float*)d_out;

    float *p_qkv, *p_q, *p_k, *p_v, *p_o;
    cudaGetSymbolAddress((void**)&p_qkv, g_qkv);
    cudaGetSymbolAddress((void**)&p_q, g_q);
    cudaGetSymbolAddress((void**)&p_k, g_k);
    cudaGetSymbolAddress((void**)&p_v, g_v);
    cudaGetSymbolAddress((void**)&p_o, g_o);

    // 1) QKV projection: [4096,3072] = x[4096,1024] @ w_qkv[3072,1024]^T
    sgemm_nt<<<dim3(3 * DIM / 128, M_TOT / 128), 256>>>(x, w_qkv, nullptr, p_qkv,
                                                        M_TOT, 3 * DIM, DIM);

    // 2) LN + RoPE + scale + transpose to [B,H,S,D]
    ln_rope_kernel<<<dim3(M_TOT, NHEADS), 64>>>(p_qkv, q_g, q_b, k_g, k_b);

    // 3) flash attention
    const int smem = (BQ * HDIM + BKT * KPAD + BKT * HDIM + BQ * BKT) * sizeof(float);
    cudaFuncSetAttribute(attn_kernel, cudaFuncAttributeMaxDynamicSharedMemorySize, smem);
    attn_kernel<<<dim3(S / BQ, B * NHEADS), 256, smem>>>(p_q, p_k, p_v, p_o);

    // 4) output projection: out[4096,1024] = O @ w_proj^T + b_proj
    sgemm_nt<<<dim3(DIM / 128, M_TOT / 128), 256>>>(p_o, w_proj, b_proj, out,
                                                    M_TOT, DIM, DIM);
}

// round 6
// speedup vs baseline: 2.4693x; 2.4693x over previous
#include <cuda_runtime.h>
#include <cuda_bf16.h>
#include <math_constants.h>

#define DIM 1024
#define NHEADS 16
#define HDIM 64
#define B 2
#define S 2048
#define M_TOT (B * S)            // 4096
#define EPS 1e-6f

// ---------------- scratch (static device globals; no allocation) ----------------
__device__ float g_qkv[(size_t)M_TOT * 3 * DIM];           // [4096, 3072]
__device__ float g_q[(size_t)B * NHEADS * S * HDIM];       // [B,H,S,D]
__device__ float g_k[(size_t)B * NHEADS * S * HDIM];
__device__ float g_v[(size_t)B * NHEADS * S * HDIM];
__device__ float g_o[(size_t)M_TOT * DIM];                 // [4096, 1024] attn output

// ---- helpers --------------------------------------------------------------------
__device__ __forceinline__ unsigned f2tf32(float x) {
    unsigned u;
    asm("cvt.rna.tf32.f32 %0, %1;" : "=r"(u) : "f"(x));
    return u;
}
__device__ __forceinline__ void mma_tf32(float c[4],
                                         unsigned a0, unsigned a1, unsigned a2, unsigned a3,
                                         unsigned b0, unsigned b1) {
    asm volatile(
        "mma.sync.aligned.m16n8k8.row.col.f32.tf32.tf32.f32 "
        "{%0,%1,%2,%3}, {%4,%5,%6,%7}, {%8,%9}, {%0,%1,%2,%3};"
        : "+f"(c[0]), "+f"(c[1]), "+f"(c[2]), "+f"(c[3])
        : "r"(a0), "r"(a1), "r"(a2), "r"(a3), "r"(b0), "r"(b1));
}

// ---------------- Kernel 1/4: tf32 tensor-core GEMM NT ---------------------------
// C[m,n] = sum_k A[m,k] * Bm[n,k] (+bias). 128x128 tile, BK=32, 256 threads.
// Warp grid 2(m) x 4(n): warp tile 64x32. Fragments straight from padded smem.
#define GSTR 36
__global__ void __launch_bounds__(256) gemm_tf32(const float* __restrict__ A,
                                                 const float* __restrict__ Bm,
                                                 const float* __restrict__ bias,
                                                 float* __restrict__ C,
                                                 int M, int N, int K) {
    __shared__ float As[128][GSTR];
    __shared__ float Bs[128][GSTR];

    const int bn = blockIdx.x * 128;
    const int bm = blockIdx.y * 128;
    const int tid = threadIdx.x;
    const int warp = tid >> 5;
    const int lane = tid & 31;
    const int wm = (warp >> 2) * 64;   // 0 or 64
    const int wn = (warp & 3) * 32;    // 0,32,64,96

    float acc[4][4][4];
#pragma unroll
    for (int mt = 0; mt < 4; mt++)
#pragma unroll
        for (int nt = 0; nt < 4; nt++)
#pragma unroll
            for (int e = 0; e < 4; e++) acc[mt][nt][e] = 0.f;

    const int ldr = tid >> 1;                 // 0..127 row within tile
    const float* Arow = A + (size_t)(bm + ldr) * K;
    const float* Brow = Bm + (size_t)(bn + ldr) * K;

    for (int k0 = 0; k0 < K; k0 += 32) {
        float4 av[4], bv[4];
#pragma unroll
        for (int i = 0; i < 4; i++) {
            int c4 = ((tid & 1) + 2 * i) * 4;
            av[i] = *(const float4*)(Arow + k0 + c4);
            bv[i] = *(const float4*)(Brow + k0 + c4);
        }
        __syncthreads();
#pragma unroll
        for (int i = 0; i < 4; i++) {
            int c4 = ((tid & 1) + 2 * i) * 4;
            float4 at, bt;
            at.x = __uint_as_float(f2tf32(av[i].x)); at.y = __uint_as_float(f2tf32(av[i].y));
            at.z = __uint_as_float(f2tf32(av[i].z)); at.w = __uint_as_float(f2tf32(av[i].w));
            bt.x = __uint_as_float(f2tf32(bv[i].x)); bt.y = __uint_as_float(f2tf32(bv[i].y));
            bt.z = __uint_as_float(f2tf32(bv[i].z)); bt.w = __uint_as_float(f2tf32(bv[i].w));
            *(float4*)(&As[ldr][c4]) = at;
            *(float4*)(&Bs[ldr][c4]) = bt;
        }
        __syncthreads();

#pragma unroll
        for (int kc = 0; kc < 4; kc++) {
            const int ko = kc * 8;
            unsigned af[4][4];
#pragma unroll
            for (int mt = 0; mt < 4; mt++) {
                int r = wm + mt * 16 + (lane >> 2);
                af[mt][0] = __float_as_uint(As[r][ko + (lane & 3)]);
                af[mt][1] = __float_as_uint(As[r + 8][ko + (lane & 3)]);
                af[mt][2] = __float_as_uint(As[r][ko + (lane & 3) + 4]);
                af[mt][3] = __float_as_uint(As[r + 8][ko + (lane & 3) + 4]);
            }
#pragma unroll
            for (int nt = 0; nt < 4; nt++) {
                int cb = wn + nt * 8 + (lane >> 2);
                unsigned b0 = __float_as_uint(Bs[cb][ko + (lane & 3)]);
                unsigned b1 = __float_as_uint(Bs[cb][ko + (lane & 3) + 4]);
#pragma unroll
                for (int mt = 0; mt < 4; mt++)
                    mma_tf32(acc[mt][nt], af[mt][0], af[mt][1], af[mt][2], af[mt][3], b0, b1);
            }
        }
        __syncthreads();
    }

    // epilogue
#pragma unroll
    for (int mt = 0; mt < 4; mt++) {
        int r0 = bm + wm + mt * 16 + (lane >> 2);
#pragma unroll
        for (int nt = 0; nt < 4; nt++) {
            int c0 = bn + wn + nt * 8 + (lane & 3) * 2;
            float bz0 = bias ? bias[c0] : 0.f;
            float bz1 = bias ? bias[c0 + 1] : 0.f;
            float2 o0 = {acc[mt][nt][0] + bz0, acc[mt][nt][1] + bz1};
            float2 o1 = {acc[mt][nt][2] + bz0, acc[mt][nt][3] + bz1};
            *(float2*)(C + (size_t)r0 * N + c0) = o0;
            *(float2*)(C + (size_t)(r0 + 8) * N + c0) = o1;
        }
    }
}

// ---------------- Kernel 2/4: per-head LayerNorm + RoPE + scale + transpose ------
__global__ void __launch_bounds__(64) ln_rope_kernel(const float* __restrict__ qkv,
                                                     const float* __restrict__ qg,
                                                     const float* __restrict__ qb,
                                                     const float* __restrict__ kg,
                                                     const float* __restrict__ kb) {
    const int m = blockIdx.x;          // b*S + s
    const int h = blockIdx.y;
    const int d = threadIdx.x;         // 0..63
    const int b = m / S;
    const int s = m % S;

    const float* row = qkv + (size_t)m * (3 * DIM);
    float qv = row[h * HDIM + d];
    float kv = row[DIM + h * HDIM + d];
    float vv = row[2 * DIM + h * HDIM + d];

    __shared__ float r1[64], r2[64];
    __shared__ float qn[64], kn[64];

    r1[d] = qv; r2[d] = qv * qv;
    __syncthreads();
    for (int st = 32; st > 0; st >>= 1) {
        if (d < st) { r1[d] += r1[d + st]; r2[d] += r2[d + st]; }
        __syncthreads();
    }
    float mu = r1[0] * (1.f / HDIM);
    float var = r2[0] * (1.f / HDIM) - mu * mu;
    float qnv = (qv - mu) * rsqrtf(var + EPS) * qg[d] + qb[d];
    __syncthreads();

    r1[d] = kv; r2[d] = kv * kv;
    __syncthreads();
    for (int st = 32; st > 0; st >>= 1) {
        if (d < st) { r1[d] += r1[d + st]; r2[d] += r2[d + st]; }
        __syncthreads();
    }
    mu = r1[0] * (1.f / HDIM);
    var = r2[0] * (1.f / HDIM) - mu * mu;
    float knv = (kv - mu) * rsqrtf(var + EPS) * kg[d] + kb[d];

    qn[d] = qnv; kn[d] = knv;
    __syncthreads();

    const int half = HDIM / 2;
    float fi = (float)(d & (half - 1)) / (float)half;
    float inv = powf(10000.f, -fi);
    float ang = (float)s * inv;
    float c, sn;
    sincosf(ang, &sn, &c);
    float qrot = (d < half) ? -qn[d + half] : qn[d - half];
    float krot = (d < half) ? -kn[d + half] : kn[d - half];
    float qo = (qnv * c + qrot * sn) * 0.125f;   // * D^-0.5
    float ko = knv * c + krot * sn;

    const size_t idx = (((size_t)(b * NHEADS + h)) * S + s) * HDIM + d;
    g_q[idx] = qo;
    g_k[idx] = ko;
    g_v[idx] = vv;
}

// ---------------- Kernel 3/4: flash attention with tf32 tensor cores -------------
// grid: (S/128, B*H), 256 threads (8 warps). Warp w owns q-rows [w*16, w*16+16).
// QK^T and PV both via m16n8k8 tf32 mma; P staged in smem (C-frag -> A-frag).
#define AQ 128
#define AKT 64
#define ASTR 68
__global__ void __launch_bounds__(256) attn_tc(const float* __restrict__ Q,
                                               const float* __restrict__ K,
                                               const float* __restrict__ V,
                                               float* __restrict__ O) {
    extern __shared__ float sm[];
    float* Qs = sm;                     // [128][68]
    float* Ks = Qs + AQ * ASTR;         // [64][68]   (key, dim)
    float* Vs = Ks + AKT * ASTR;        // [64][68]   (dim, key)  transposed
    float* Ps = Vs + AKT * ASTR;        // [128][68]  (q, key)

    const int bh = blockIdx.y;
    const int qt = blockIdx.x;
    const int b = bh / NHEADS;
    const int h = bh % NHEADS;

    const float* Qg = Q + ((size_t)bh * S + qt * AQ) * HDIM;
    const float* Kg = K + (size_t)bh * S * HDIM;
    const float* Vg = V + (size_t)bh * S * HDIM;

    const int tid = threadIdx.x;
    const int warp = tid >> 5;
    const int lane = tid & 31;
    const int wq = warp * 16;
    const int qr = lane >> 2;       // 0..7
    const int ql = lane & 3;        // 0..3

    // load Q tile (128x64) with tf32 convert
#pragma unroll
    for (int i = 0; i < 8; i++) {
        int f = tid + i * 256;
        int r = f >> 4, c4 = (f & 15) * 4;
        float4 q4 = *(const float4*)(Qg + r * HDIM + c4);
        float4 qs;
        qs.x = __uint_as_float(f2tf32(q4.x)); qs.y = __uint_as_float(f2tf32(q4.y));
        qs.z = __uint_as_float(f2tf32(q4.z)); qs.w = __uint_as_float(f2tf32(q4.w));
        *(float4*)(&Qs[r * ASTR + c4]) = qs;
    }

    float ofrag[8][4];
#pragma unroll
    for (int dt = 0; dt < 8; dt++)
#pragma unroll
        for (int e = 0; e < 4; e++) ofrag[dt][e] = 0.f;
    float mrow0 = -CUDART_INF_F, mrow1 = -CUDART_INF_F;
    float lrow0 = 0.f, lrow1 = 0.f;
    __syncthreads();

    for (int kt = 0; kt < S / AKT; kt++) {
        const float* Kt = Kg + (size_t)kt * AKT * HDIM;
        const float* Vt = Vg + (size_t)kt * AKT * HDIM;
#pragma unroll
        for (int i = 0; i < 4; i++) {
            int f = tid + i * 256;
            int r = f >> 4, c4 = (f & 15) * 4;
            float4 k4 = *(const float4*)(Kt + r * HDIM + c4);
            float4 ks;
            ks.x = __uint_as_float(f2tf32(k4.x)); ks.y = __uint_as_float(f2tf32(k4.y));
            ks.z = __uint_as_float(f2tf32(k4.z)); ks.w = __uint_as_float(f2tf32(k4.w));
            *(float4*)(&Ks[r * ASTR + c4]) = ks;
            float4 v4 = *(const float4*)(Vt + r * HDIM + c4);
            Vs[(c4 + 0) * ASTR + r] = __uint_as_float(f2tf32(v4.x));
            Vs[(c4 + 1) * ASTR + r] = __uint_as_float(f2tf32(v4.y));
            Vs[(c4 + 2) * ASTR + r] = __uint_as_float(f2tf32(v4.z));
            Vs[(c4 + 3) * ASTR + r] = __uint_as_float(f2tf32(v4.w));
        }
        __syncthreads();

        // ---- scores: 16 x 64 per warp ----
        float sf[8][4];
#pragma unroll
        for (int nt = 0; nt < 8; nt++)
#pragma unroll
            for (int e = 0; e < 4; e++) sf[nt][e] = 0.f;

#pragma unroll
        for (int kc = 0; kc < 8; kc++) {
            const int ko = kc * 8;
            int r = wq + qr;
            unsigned a0 = __float_as_uint(Qs[r * ASTR + ko + ql]);
            unsigned a1 = __float_as_uint(Qs[(r + 8) * ASTR + ko + ql]);
            unsigned a2 = __float_as_uint(Qs[r * ASTR + ko + ql + 4]);
            unsigned a3 = __float_as_uint(Qs[(r + 8) * ASTR + ko + ql + 4]);
#pragma unroll
            for (int nt = 0; nt < 8; nt++) {
                int cb = nt * 8 + qr;
                unsigned b0 = __float_as_uint(Ks[cb * ASTR + ko + ql]);
                unsigned b1 = __float_as_uint(Ks[cb * ASTR + ko + ql + 4]);
                mma_tf32(sf[nt], a0, a1, a2, a3, b0, b1);
            }
        }

        // ---- online softmax ----
        float mx0 = -CUDART_INF_F, mx1 = -CUDART_INF_F;
#pragma unroll
        for (int nt = 0; nt < 8; nt++) {
            mx0 = fmaxf(mx0, fmaxf(sf[nt][0], sf[nt][1]));
            mx1 = fmaxf(mx1, fmaxf(sf[nt][2], sf[nt][3]));
        }
        mx0 = fmaxf(mx0, __shfl_xor_sync(0xffffffffu, mx0, 1));
        mx0 = fmaxf(mx0, __shfl_xor_sync(0xffffffffu, mx0, 2));
        mx1 = fmaxf(mx1, __shfl_xor_sync(0xffffffffu, mx1, 1));
        mx1 = fmaxf(mx1, __shfl_xor_sync(0xffffffffu, mx1, 2));
        float nm0 = fmaxf(mrow0, mx0);
        float nm1 = fmaxf(mrow1, mx1);
        float corr0 = __expf(mrow0 - nm0);
        float corr1 = __expf(mrow1 - nm1);

        float sum0 = 0.f, sum1 = 0.f;
        const int r1 = wq + qr, r2 = r1 + 8;
#pragma unroll
        for (int nt = 0; nt < 8; nt++) {
            float p0 = __expf(sf[nt][0] - nm0);
            float p1 = __expf(sf[nt][1] - nm0);
            float p2 = __expf(sf[nt][2] - nm1);
            float p3 = __expf(sf[nt][3] - nm1);
            sum0 += p0 + p1;
            sum1 += p2 + p3;
            int c = nt * 8 + ql * 2;
            float2 s01 = {__uint_as_float(f2tf32(p0)), __uint_as_float(f2tf32(p1))};
            float2 s23 = {__uint_as_float(f2tf32(p2)), __uint_as_float(f2tf32(p3))};
            *(float2*)(&Ps[r1 * ASTR + c]) = s01;
            *(float2*)(&Ps[r2 * ASTR + c]) = s23;
        }
        sum0 += __shfl_xor_sync(0xffffffffu, sum0, 1);
        sum0 += __shfl_xor_sync(0xffffffffu, sum0, 2);
        sum1 += __shfl_xor_sync(0xffffffffu, sum1, 1);
        sum1 += __shfl_xor_sync(0xffffffffu, sum1, 2);
        lrow0 = lrow0 * corr0 + sum0;
        lrow1 = lrow1 * corr1 + sum1;
        mrow0 = nm0; mrow1 = nm1;
#pragma unroll
        for (int dt = 0; dt < 8; dt++) {
            ofrag[dt][0] *= corr0; ofrag[dt][1] *= corr0;
            ofrag[dt][2] *= corr1; ofrag[dt][3] *= corr1;
        }
        __syncwarp();

        // ---- PV: O[16 x 64] += P[16 x 64] @ V[64 x 64] ----
#pragma unroll
        for (int kc = 0; kc < 8; kc++) {
            const int ko = kc * 8;
            unsigned a0 = __float_as_uint(Ps[r1 * ASTR + ko + ql]);
            unsigned a1 = __float_as_uint(Ps[r2 * ASTR + ko + ql]);
            unsigned a2 = __float_as_uint(Ps[r1 * ASTR + ko + ql + 4]);
            unsigned a3 = __float_as_uint(Ps[r2 * ASTR + ko + ql + 4]);
#pragma unroll
            for (int dt = 0; dt < 8; dt++) {
                int db = dt * 8 + qr;
                unsigned b0 = __float_as_uint(Vs[db * ASTR + ko + ql]);
                unsigned b1 = __float_as_uint(Vs[db * ASTR + ko + ql + 4]);
                mma_tf32(ofrag[dt], a0, a1, a2, a3, b0, b1);
            }
        }
        __syncthreads();
    }

    // epilogue: write to [B,S,C] at column h*64
    const float inv0 = 1.f / lrow0;
    const float inv1 = 1.f / lrow1;
    const int r1g = qt * AQ + wq + qr;
#pragma unroll
    for (int dt = 0; dt < 8; dt++) {
        int c = dt * 8 + ql * 2;
        size_t o1 = ((size_t)b * S + r1g) * DIM + h * HDIM + c;
        size_t o2 = ((size_t)b * S + r1g + 8) * DIM + h * HDIM + c;
        float2 w1 = {ofrag[dt][0] * inv0, ofrag[dt][1] * inv0};
        float2 w2 = {ofrag[dt][2] * inv1, ofrag[dt][3] * inv1};
        *(float2*)(O + o1) = w1;
        *(float2*)(O + o2) = w2;
    }
}

// ---------------- launch ---------------------------------------------------------
extern "C" void kernel_launch(void* const* d_in, const int* in_sizes, int n_in,
                              void* d_out, int out_size) {
    const float* x      = (const float*)d_in[0];
    const float* w_qkv  = (const float*)d_in[1];
    const float* w_proj = (const float*)d_in[2];
    const float* b_proj = (const float*)d_in[3];
    const float* q_g    = (const float*)d_in[4];
    const float* q_b    = (const float*)d_in[5];
    const float* k_g    = (const float*)d_in[6];
    const float* k_b    = (const float*)d_in[7];
    float* out = (float*)d_out;

    float *p_qkv, *p_q, *p_k, *p_v, *p_o;
    cudaGetSymbolAddress((void**)&p_qkv, g_qkv);
    cudaGetSymbolAddress((void**)&p_q, g_q);
    cudaGetSymbolAddress((void**)&p_k, g_k);
    cudaGetSymbolAddress((void**)&p_v, g_v);
    cudaGetSymbolAddress((void**)&p_o, g_o);

    // 1) QKV projection: [4096,3072] = x @ w_qkv^T
    gemm_tf32<<<dim3(3 * DIM / 128, M_TOT / 128), 256>>>(x, w_qkv, nullptr, p_qkv,
                                                         M_TOT, 3 * DIM, DIM);

    // 2) LN + RoPE + scale + transpose to [B,H,S,D]
    ln_rope_kernel<<<dim3(M_TOT, NHEADS), 64>>>(p_qkv, q_g, q_b, k_g, k_b);

    // 3) flash attention (tensor core)
    const int smem = (AQ * ASTR + AKT * ASTR + AKT * ASTR + AQ * ASTR) * sizeof(float);
    cudaFuncSetAttribute(attn_tc, cudaFuncAttributeMaxDynamicSharedMemorySize, smem);
    attn_tc<<<dim3(S / AQ, B * NHEADS), 256, smem>>>(p_q, p_k, p_v, p_o);

    // 4) output projection: out = O @ w_proj^T + b_proj
    gemm_tf32<<<dim3(DIM / 128, M_TOT / 128), 256>>>(p_o, w_proj, b_proj, out,
                                                     M_TOT, DIM, DIM);
}

// round 7
// speedup vs baseline: 2.6359x; 1.0675x over previous
#include <cuda_runtime.h>
#include <cuda_bf16.h>
#include <math_constants.h>

#define DIM 1024
#define NHEADS 16
#define HDIM 64
#define B 2
#define S 2048
#define M_TOT (B * S)            // 4096
#define EPS 1e-6f

// ---------------- scratch (static device globals; no allocation) ----------------
__device__ float g_qkv[(size_t)M_TOT * 3 * DIM];           // [4096, 3072]
__device__ float g_q[(size_t)B * NHEADS * S * HDIM];       // [B,H,S,D]
__device__ float g_k[(size_t)B * NHEADS * S * HDIM];
__device__ float g_v[(size_t)B * NHEADS * S * HDIM];
__device__ float g_o[(size_t)M_TOT * DIM];                 // [4096, 1024] attn output

// ---- helpers --------------------------------------------------------------------
__device__ __forceinline__ unsigned f2tf32(float x) {
    unsigned u;
    asm("cvt.rna.tf32.f32 %0, %1;" : "=r"(u) : "f"(x));
    return u;
}
__device__ __forceinline__ float f2tf32f(float x) { return __uint_as_float(f2tf32(x)); }
__device__ __forceinline__ void mma_tf32(float c[4],
                                         unsigned a0, unsigned a1, unsigned a2, unsigned a3,
                                         unsigned b0, unsigned b1) {
    asm volatile(
        "mma.sync.aligned.m16n8k8.row.col.f32.tf32.tf32.f32 "
        "{%0,%1,%2,%3}, {%4,%5,%6,%7}, {%8,%9}, {%0,%1,%2,%3};"
        : "+f"(c[0]), "+f"(c[1]), "+f"(c[2]), "+f"(c[3])
        : "r"(a0), "r"(a1), "r"(a2), "r"(a3), "r"(b0), "r"(b1));
}

// ---------------- Kernel 1/4: tf32 GEMM NT, double-buffered ----------------------
// C[m,n] = sum_k A[m,k]*Bm[n,k] (+bias). 128x128 tile, BK=32, 256 thr, 2 blk/SM.
#define GSTR 36
#define GBUF (128 * GSTR)
__global__ void __launch_bounds__(256, 2) gemm_tf32(const float* __restrict__ A,
                                                    const float* __restrict__ Bm,
                                                    const float* __restrict__ bias,
                                                    float* __restrict__ C,
                                                    int M, int N, int K) {
    extern __shared__ float gsm[];
    float* As = gsm;              // [2][128][GSTR]
    float* Bs = gsm + 2 * GBUF;   // [2][128][GSTR]

    const int bn = blockIdx.x * 128;
    const int bm = blockIdx.y * 128;
    const int tid = threadIdx.x;
    const int warp = tid >> 5;
    const int lane = tid & 31;
    const int wm = (warp >> 2) * 64;   // 0 or 64
    const int wn = (warp & 3) * 32;    // 0,32,64,96

    float acc[4][4][4];
#pragma unroll
    for (int mt = 0; mt < 4; mt++)
#pragma unroll
        for (int nt = 0; nt < 4; nt++)
#pragma unroll
            for (int e = 0; e < 4; e++) acc[mt][nt][e] = 0.f;

    const int ldr = tid >> 1;                 // 0..127 row within tile
    const float* Arow = A + (size_t)(bm + ldr) * K;
    const float* Brow = Bm + (size_t)(bn + ldr) * K;

    float4 av[4], bv[4];
    // prologue: load + store slab 0
#pragma unroll
    for (int i = 0; i < 4; i++) {
        int c4 = ((tid & 1) + 2 * i) * 4;
        av[i] = *(const float4*)(Arow + c4);
        bv[i] = *(const float4*)(Brow + c4);
    }
#pragma unroll
    for (int i = 0; i < 4; i++) {
        int c4 = ((tid & 1) + 2 * i) * 4;
        float* ap = &As[ldr * GSTR + c4];
        float* bp = &Bs[ldr * GSTR + c4];
        ap[0] = f2tf32f(av[i].x); ap[1] = f2tf32f(av[i].y);
        ap[2] = f2tf32f(av[i].z); ap[3] = f2tf32f(av[i].w);
        bp[0] = f2tf32f(bv[i].x); bp[1] = f2tf32f(bv[i].y);
        bp[2] = f2tf32f(bv[i].z); bp[3] = f2tf32f(bv[i].w);
    }
    __syncthreads();

    const int nit = K >> 5;
    for (int it = 0; it < nit; it++) {
        const int cur = it & 1;
        // prefetch next slab (overlaps with MMA below)
        if (it + 1 < nit) {
            const int k0 = (it + 1) << 5;
#pragma unroll
            for (int i = 0; i < 4; i++) {
                int c4 = ((tid & 1) + 2 * i) * 4;
                av[i] = *(const float4*)(Arow + k0 + c4);
                bv[i] = *(const float4*)(Brow + k0 + c4);
            }
        }

        const float* Ac = As + cur * GBUF;
        const float* Bc = Bs + cur * GBUF;
#pragma unroll
        for (int kc = 0; kc < 4; kc++) {
            const int ko = kc * 8;
            unsigned af[4][4];
#pragma unroll
            for (int mt = 0; mt < 4; mt++) {
                int r = wm + mt * 16 + (lane >> 2);
                af[mt][0] = __float_as_uint(Ac[r * GSTR + ko + (lane & 3)]);
                af[mt][1] = __float_as_uint(Ac[(r + 8) * GSTR + ko + (lane & 3)]);
                af[mt][2] = __float_as_uint(Ac[r * GSTR + ko + (lane & 3) + 4]);
                af[mt][3] = __float_as_uint(Ac[(r + 8) * GSTR + ko + (lane & 3) + 4]);
            }
#pragma unroll
            for (int nt = 0; nt < 4; nt++) {
                int cb = wn + nt * 8 + (lane >> 2);
                unsigned b0 = __float_as_uint(Bc[cb * GSTR + ko + (lane & 3)]);
                unsigned b1 = __float_as_uint(Bc[cb * GSTR + ko + (lane & 3) + 4]);
#pragma unroll
                for (int mt = 0; mt < 4; mt++)
                    mma_tf32(acc[mt][nt], af[mt][0], af[mt][1], af[mt][2], af[mt][3], b0, b1);
            }
        }

        if (it + 1 < nit) {
            const int nxt = (it + 1) & 1;
            float* An = As + nxt * GBUF;
            float* Bn = Bs + nxt * GBUF;
#pragma unroll
            for (int i = 0; i < 4; i++) {
                int c4 = ((tid & 1) + 2 * i) * 4;
                float* ap = &An[ldr * GSTR + c4];
                float* bp = &Bn[ldr * GSTR + c4];
                ap[0] = f2tf32f(av[i].x); ap[1] = f2tf32f(av[i].y);
                ap[2] = f2tf32f(av[i].z); ap[3] = f2tf32f(av[i].w);
                bp[0] = f2tf32f(bv[i].x); bp[1] = f2tf32f(bv[i].y);
                bp[2] = f2tf32f(bv[i].z); bp[3] = f2tf32f(bv[i].w);
            }
        }
        __syncthreads();
    }

    // epilogue
#pragma unroll
    for (int mt = 0; mt < 4; mt++) {
        int r0 = bm + wm + mt * 16 + (lane >> 2);
#pragma unroll
        for (int nt = 0; nt < 4; nt++) {
            int c0 = bn + wn + nt * 8 + (lane & 3) * 2;
            float bz0 = bias ? bias[c0] : 0.f;
            float bz1 = bias ? bias[c0 + 1] : 0.f;
            float2 o0 = {acc[mt][nt][0] + bz0, acc[mt][nt][1] + bz1};
            float2 o1 = {acc[mt][nt][2] + bz0, acc[mt][nt][3] + bz1};
            *(float2*)(C + (size_t)r0 * N + c0) = o0;
            *(float2*)(C + (size_t)(r0 + 8) * N + c0) = o1;
        }
    }
}

// ---------------- Kernel 2/4: LN + RoPE, warp-per-head (no smem, no bar) ---------
// grid: M_TOT, block: 512 (16 warps = 16 heads). Lane owns dims {lane, lane+32}.
__global__ void __launch_bounds__(512) ln_rope_kernel(const float* __restrict__ qkv,
                                                      const float* __restrict__ qg,
                                                      const float* __restrict__ qb,
                                                      const float* __restrict__ kg,
                                                      const float* __restrict__ kb) {
    const int m = blockIdx.x;              // b*S + s
    const int h = threadIdx.x >> 5;
    const int lane = threadIdx.x & 31;
    const int b = m / S;
    const int s = m % S;

    const float* row = qkv + (size_t)m * (3 * DIM) + h * HDIM;
    float q0 = row[lane],           q1 = row[lane + 32];
    float k0 = row[DIM + lane],     k1 = row[DIM + lane + 32];
    float v0 = row[2 * DIM + lane], v1 = row[2 * DIM + lane + 32];

    float sq = q0 + q1, sq2 = q0 * q0 + q1 * q1;
    float sk = k0 + k1, sk2 = k0 * k0 + k1 * k1;
#pragma unroll
    for (int o = 16; o; o >>= 1) {
        sq  += __shfl_xor_sync(0xffffffffu, sq, o);
        sq2 += __shfl_xor_sync(0xffffffffu, sq2, o);
        sk  += __shfl_xor_sync(0xffffffffu, sk, o);
        sk2 += __shfl_xor_sync(0xffffffffu, sk2, o);
    }
    float muq = sq * (1.f / HDIM);
    float rq = rsqrtf(sq2 * (1.f / HDIM) - muq * muq + EPS);
    float muk = sk * (1.f / HDIM);
    float rk = rsqrtf(sk2 * (1.f / HDIM) - muk * muk + EPS);

    float qn0 = (q0 - muq) * rq * qg[lane] + qb[lane];
    float qn1 = (q1 - muq) * rq * qg[lane + 32] + qb[lane + 32];
    float kn0 = (k0 - muk) * rk * kg[lane] + kb[lane];
    float kn1 = (k1 - muk) * rk * kg[lane + 32] + kb[lane + 32];

    // RoPE: lane holds pair (d, d+32); rotate_half -> (-x2, x1)
    float inv = powf(10000.f, -(float)lane * (1.f / 32.f));
    float c, sn;
    sincosf((float)s * inv, &sn, &c);
    float qo0 = (qn0 * c - qn1 * sn) * 0.125f;
    float qo1 = (qn1 * c + qn0 * sn) * 0.125f;
    float ko0 = kn0 * c - kn1 * sn;
    float ko1 = kn1 * c + kn0 * sn;

    const size_t idx = (((size_t)(b * NHEADS + h)) * S + s) * HDIM;
    g_q[idx + lane] = qo0;  g_q[idx + lane + 32] = qo1;
    g_k[idx + lane] = ko0;  g_k[idx + lane + 32] = ko1;
    g_v[idx + lane] = v0;   g_v[idx + lane + 32] = v1;
}

// ---------------- Kernel 3/4: flash attention, tf32, double-buffered K/V ---------
#define AQ 128
#define AKT 64
#define ASTR 68
#define KVBUF (AKT * ASTR)
__global__ void __launch_bounds__(256) attn_tc(const float* __restrict__ Q,
                                               const float* __restrict__ K,
                                               const float* __restrict__ V,
                                               float* __restrict__ O) {
    extern __shared__ float sm[];
    float* Qs = sm;                       // [128][68]
    float* Ks = Qs + AQ * ASTR;           // [2][64][68]  (key, dim)
    float* Vs = Ks + 2 * KVBUF;           // [2][64][68]  (dim, key) transposed
    float* Ps = Vs + 2 * KVBUF;           // [128][68]

    const int bh = blockIdx.y;
    const int qt = blockIdx.x;
    const int b = bh / NHEADS;
    const int h = bh % NHEADS;

    const float* Qg = Q + ((size_t)bh * S + qt * AQ) * HDIM;
    const float* Kg = K + (size_t)bh * S * HDIM;
    const float* Vg = V + (size_t)bh * S * HDIM;

    const int tid = threadIdx.x;
    const int warp = tid >> 5;
    const int lane = tid & 31;
    const int wq = warp * 16;
    const int qr = lane >> 2;       // 0..7
    const int ql = lane & 3;        // 0..3
    const int lr = tid >> 4;        // 0..15 row group for loads
    const int lc4 = (tid & 15) * 4; // col*4 for loads

    // load Q tile (128x64), tf32 convert
#pragma unroll
    for (int i = 0; i < 8; i++) {
        int r = lr + i * 16;
        float4 q4 = *(const float4*)(Qg + r * HDIM + lc4);
        float* qp = &Qs[r * ASTR + lc4];
        qp[0] = f2tf32f(q4.x); qp[1] = f2tf32f(q4.y);
        qp[2] = f2tf32f(q4.z); qp[3] = f2tf32f(q4.w);
    }

    float ofrag[8][4];
#pragma unroll
    for (int dt = 0; dt < 8; dt++)
#pragma unroll
        for (int e = 0; e < 4; e++) ofrag[dt][e] = 0.f;
    float mrow0 = -CUDART_INF_F, mrow1 = -CUDART_INF_F;
    float lrow0 = 0.f, lrow1 = 0.f;

    float4 kr[4], vr[4];
    // prologue: load tile 0 into regs, then store into buffer 0
#pragma unroll
    for (int i = 0; i < 4; i++) {
        int r = lr + i * 16;
        kr[i] = *(const float4*)(Kg + r * HDIM + lc4);
        vr[i] = *(const float4*)(Vg + r * HDIM + lc4);
    }
#pragma unroll
    for (int i = 0; i < 4; i++) {
        int r = lr + i * 16;
        float* kp = &Ks[r * ASTR + lc4];
        kp[0] = f2tf32f(kr[i].x); kp[1] = f2tf32f(kr[i].y);
        kp[2] = f2tf32f(kr[i].z); kp[3] = f2tf32f(kr[i].w);
        Vs[(lc4 + 0) * ASTR + r] = f2tf32f(vr[i].x);
        Vs[(lc4 + 1) * ASTR + r] = f2tf32f(vr[i].y);
        Vs[(lc4 + 2) * ASTR + r] = f2tf32f(vr[i].z);
        Vs[(lc4 + 3) * ASTR + r] = f2tf32f(vr[i].w);
    }
    __syncthreads();

    const int nkt = S / AKT;
    for (int kt = 0; kt < nkt; kt++) {
        const int cur = kt & 1;
        // prefetch tile kt+1
        if (kt + 1 < nkt) {
            const float* Kt = Kg + (size_t)(kt + 1) * AKT * HDIM;
            const float* Vt = Vg + (size_t)(kt + 1) * AKT * HDIM;
#pragma unroll
            for (int i = 0; i < 4; i++) {
                int r = lr + i * 16;
                kr[i] = *(const float4*)(Kt + r * HDIM + lc4);
                vr[i] = *(const float4*)(Vt + r * HDIM + lc4);
            }
        }
        const float* Kc = Ks + cur * KVBUF;
        const float* Vc = Vs + cur * KVBUF;

        // ---- scores: 16 x 64 per warp ----
        float sf[8][4];
#pragma unroll
        for (int nt = 0; nt < 8; nt++)
#pragma unroll
            for (int e = 0; e < 4; e++) sf[nt][e] = 0.f;

#pragma unroll
        for (int kc = 0; kc < 8; kc++) {
            const int ko = kc * 8;
            int r = wq + qr;
            unsigned a0 = __float_as_uint(Qs[r * ASTR + ko + ql]);
            unsigned a1 = __float_as_uint(Qs[(r + 8) * ASTR + ko + ql]);
            unsigned a2 = __float_as_uint(Qs[r * ASTR + ko + ql + 4]);
            unsigned a3 = __float_as_uint(Qs[(r + 8) * ASTR + ko + ql + 4]);
#pragma unroll
            for (int nt = 0; nt < 8; nt++) {
                int cb = nt * 8 + qr;
                unsigned b0 = __float_as_uint(Kc[cb * ASTR + ko + ql]);
                unsigned b1 = __float_as_uint(Kc[cb * ASTR + ko + ql + 4]);
                mma_tf32(sf[nt], a0, a1, a2, a3, b0, b1);
            }
        }

        // ---- online softmax ----
        float mx0 = -CUDART_INF_F, mx1 = -CUDART_INF_F;
#pragma unroll
        for (int nt = 0; nt < 8; nt++) {
            mx0 = fmaxf(mx0, fmaxf(sf[nt][0], sf[nt][1]));
            mx1 = fmaxf(mx1, fmaxf(sf[nt][2], sf[nt][3]));
        }
        mx0 = fmaxf(mx0, __shfl_xor_sync(0xffffffffu, mx0, 1));
        mx0 = fmaxf(mx0, __shfl_xor_sync(0xffffffffu, mx0, 2));
        mx1 = fmaxf(mx1, __shfl_xor_sync(0xffffffffu, mx1, 1));
        mx1 = fmaxf(mx1, __shfl_xor_sync(0xffffffffu, mx1, 2));
        float nm0 = fmaxf(mrow0, mx0);
        float nm1 = fmaxf(mrow1, mx1);
        float corr0 = __expf(mrow0 - nm0);
        float corr1 = __expf(mrow1 - nm1);

        float sum0 = 0.f, sum1 = 0.f;
        const int r1 = wq + qr, r2 = r1 + 8;
#pragma unroll
        for (int nt = 0; nt < 8; nt++) {
            float p0 = __expf(sf[nt][0] - nm0);
            float p1 = __expf(sf[nt][1] - nm0);
            float p2 = __expf(sf[nt][2] - nm1);
            float p3 = __expf(sf[nt][3] - nm1);
            sum0 += p0 + p1;
            sum1 += p2 + p3;
            int c = nt * 8 + ql * 2;
            float2 s01 = {f2tf32f(p0), f2tf32f(p1)};
            float2 s23 = {f2tf32f(p2), f2tf32f(p3)};
            *(float2*)(&Ps[r1 * ASTR + c]) = s01;
            *(float2*)(&Ps[r2 * ASTR + c]) = s23;
        }
        sum0 += __shfl_xor_sync(0xffffffffu, sum0, 1);
        sum0 += __shfl_xor_sync(0xffffffffu, sum0, 2);
        sum1 += __shfl_xor_sync(0xffffffffu, sum1, 1);
        sum1 += __shfl_xor_sync(0xffffffffu, sum1, 2);
        lrow0 = lrow0 * corr0 + sum0;
        lrow1 = lrow1 * corr1 + sum1;
        mrow0 = nm0; mrow1 = nm1;
#pragma unroll
        for (int dt = 0; dt < 8; dt++) {
            ofrag[dt][0] *= corr0; ofrag[dt][1] *= corr0;
            ofrag[dt][2] *= corr1; ofrag[dt][3] *= corr1;
        }
        __syncwarp();

        // ---- PV: O[16 x 64] += P[16 x 64] @ V[64 x 64] ----
#pragma unroll
        for (int kc = 0; kc < 8; kc++) {
            const int ko = kc * 8;
            unsigned a0 = __float_as_uint(Ps[r1 * ASTR + ko + ql]);
            unsigned a1 = __float_as_uint(Ps[r2 * ASTR + ko + ql]);
            unsigned a2 = __float_as_uint(Ps[r1 * ASTR + ko + ql + 4]);
            unsigned a3 = __float_as_uint(Ps[r2 * ASTR + ko + ql + 4]);
#pragma unroll
            for (int dt = 0; dt < 8; dt++) {
                int db = dt * 8 + qr;
                unsigned b0 = __float_as_uint(Vc[db * ASTR + ko + ql]);
                unsigned b1 = __float_as_uint(Vc[db * ASTR + ko + ql + 4]);
                mma_tf32(ofrag[dt], a0, a1, a2, a3, b0, b1);
            }
        }

        // store prefetched tile into the other buffer
        if (kt + 1 < nkt) {
            const int nxt = (kt + 1) & 1;
            float* Kn = Ks + nxt * KVBUF;
            float* Vn = Vs + nxt * KVBUF;
#pragma unroll
            for (int i = 0; i < 4; i++) {
                int r = lr + i * 16;
                float* kp = &Kn[r * ASTR + lc4];
                kp[0] = f2tf32f(kr[i].x); kp[1] = f2tf32f(kr[i].y);
                kp[2] = f2tf32f(kr[i].z); kp[3] = f2tf32f(kr[i].w);
                Vn[(lc4 + 0) * ASTR + r] = f2tf32f(vr[i].x);
                Vn[(lc4 + 1) * ASTR + r] = f2tf32f(vr[i].y);
                Vn[(lc4 + 2) * ASTR + r] = f2tf32f(vr[i].z);
                Vn[(lc4 + 3) * ASTR + r] = f2tf32f(vr[i].w);
            }
        }
        __syncthreads();
    }

    // epilogue: write to [B,S,C] at column h*64
    const float inv0 = 1.f / lrow0;
    const float inv1 = 1.f / lrow1;
    const int r1g = qt * AQ + wq + qr;
#pragma unroll
    for (int dt = 0; dt < 8; dt++) {
        int c = dt * 8 + ql * 2;
        size_t o1 = ((size_t)b * S + r1g) * DIM + h * HDIM + c;
        size_t o2 = ((size_t)b * S + r1g + 8) * DIM + h * HDIM + c;
        float2 w1 = {ofrag[dt][0] * inv0, ofrag[dt][1] * inv0};
        float2 w2 = {ofrag[dt][2] * inv1, ofrag[dt][3] * inv1};
        *(float2*)(O + o1) = w1;
        *(float2*)(O + o2) = w2;
    }
}

// ---------------- launch ---------------------------------------------------------
extern "C" void kernel_launch(void* const* d_in, const int* in_sizes, int n_in,
                              void* d_out, int out_size) {
    const float* x      = (const float*)d_in[0];
    const float* w_qkv  = (const float*)d_in[1];
    const float* w_proj = (const float*)d_in[2];
    const float* b_proj = (const float*)d_in[3];
    const float* q_g    = (const float*)d_in[4];
    const float* q_b    = (const float*)d_in[5];
    const float* k_g    = (const float*)d_in[6];
    const float* k_b    = (const float*)d_in[7];
    float* out = (float*)d_out;

    float *p_qkv, *p_q, *p_k, *p_v, *p_o;
    cudaGetSymbolAddress((void**)&p_qkv, g_qkv);
    cudaGetSymbolAddress((void**)&p_q, g_q);
    cudaGetSymbolAddress((void**)&p_k, g_k);
    cudaGetSymbolAddress((void**)&p_v, g_v);
    cudaGetSymbolAddress((void**)&p_o, g_o);

    const int gemm_smem = 4 * GBUF * sizeof(float);   // 2 bufs x (As+Bs)
    cudaFuncSetAttribute(gemm_tf32, cudaFuncAttributeMaxDynamicSharedMemorySize, gemm_smem);

    // 1) QKV projection: [4096,3072] = x @ w_qkv^T
    gemm_tf32<<<dim3(3 * DIM / 128, M_TOT / 128), 256, gemm_smem>>>(
        x, w_qkv, nullptr, p_qkv, M_TOT, 3 * DIM, DIM);

    // 2) LN + RoPE + scale + transpose to [B,H,S,D]
    ln_rope_kernel<<<M_TOT, 512>>>(p_qkv, q_g, q_b, k_g, k_b);

    // 3) flash attention (tensor core, double-buffered K/V)
    const int attn_smem = (AQ * ASTR + 4 * KVBUF + AQ * ASTR) * sizeof(float);
    cudaFuncSetAttribute(attn_tc, cudaFuncAttributeMaxDynamicSharedMemorySize, attn_smem);
    attn_tc<<<dim3(S / AQ, B * NHEADS), 256, attn_smem>>>(p_q, p_k, p_v, p_o);

    // 4) output projection: out = O @ w_proj^T + b_proj
    gemm_tf32<<<dim3(DIM / 128, M_TOT / 128), 256, gemm_smem>>>(
        p_o, w_proj, b_proj, out, M_TOT, DIM, DIM);
}

// round 8
// speedup vs baseline: 3.1383x; 1.1906x over previous
#include <cuda_runtime.h>
#include <cuda_bf16.h>
#include <math_constants.h>

#define DIM 1024
#define NHEADS 16
#define HDIM 64
#define B 2
#define S 2048
#define M_TOT (B * S)            // 4096
#define EPS 1e-6f

// ---------------- scratch (static device globals; no allocation) ----------------
__device__ float g_qkv[(size_t)M_TOT * 3 * DIM];           // [4096, 3072]
__device__ float g_q[(size_t)B * NHEADS * S * HDIM];       // [B,H,S,D]
__device__ float g_k[(size_t)B * NHEADS * S * HDIM];
__device__ float g_v[(size_t)B * NHEADS * S * HDIM];
__device__ float g_o[(size_t)M_TOT * DIM];                 // [4096, 1024] attn output

// ---- helpers --------------------------------------------------------------------
__device__ __forceinline__ unsigned f2tf32(float x) {
    unsigned u;
    asm("cvt.rna.tf32.f32 %0, %1;" : "=r"(u) : "f"(x));
    return u;
}
__device__ __forceinline__ float f2tf32f(float x) { return __uint_as_float(f2tf32(x)); }
__device__ __forceinline__ void mma_tf32(float c[4],
                                         unsigned a0, unsigned a1, unsigned a2, unsigned a3,
                                         unsigned b0, unsigned b1) {
    asm volatile(
        "mma.sync.aligned.m16n8k8.row.col.f32.tf32.tf32.f32 "
        "{%0,%1,%2,%3}, {%4,%5,%6,%7}, {%8,%9}, {%0,%1,%2,%3};"
        : "+f"(c[0]), "+f"(c[1]), "+f"(c[2]), "+f"(c[3])
        : "r"(a0), "r"(a1), "r"(a2), "r"(a3), "r"(b0), "r"(b1));
}
__device__ __forceinline__ void cp16(void* sdst, const void* gsrc) {
    unsigned sa = (unsigned)__cvta_generic_to_shared(sdst);
    asm volatile("cp.async.cg.shared.global [%0], [%1], 16;\n" :: "r"(sa), "l"(gsrc));
}
#define CP_COMMIT() asm volatile("cp.async.commit_group;\n" ::: "memory")
#define CP_WAIT0()  asm volatile("cp.async.wait_group 0;\n" ::: "memory")

// ---------------- Kernel 1/4: tf32 GEMM NT, 256x128 tile, cp.async DB ------------
// C[m,n] = sum_k A[m,k]*Bm[n,k] (+bias). 8 warps of 64x64. fp32 in smem, cvt at
// fragment load (identical numerics to cvt-on-store).
#define GSTR 36
#define GABUF (256 * GSTR)
#define GBBUF (128 * GSTR)
__global__ void __launch_bounds__(256) gemm_tf32(const float* __restrict__ A,
                                                 const float* __restrict__ Bm,
                                                 const float* __restrict__ bias,
                                                 float* __restrict__ C,
                                                 int M, int N, int K) {
    extern __shared__ float gsm[];
    float* As = gsm;                  // [2][256][GSTR]
    float* Bs = gsm + 2 * GABUF;      // [2][128][GSTR]

    const int bn = blockIdx.x * 128;
    const int bm = blockIdx.y * 256;
    const int tid = threadIdx.x;
    const int warp = tid >> 5;
    const int lane = tid & 31;
    const int wm = (warp >> 1) * 64;   // 0,64,128,192
    const int wn = (warp & 1) * 64;    // 0,64
    const int qr = lane >> 2;
    const int ql = lane & 3;

    float acc[4][8][4];
#pragma unroll
    for (int mt = 0; mt < 4; mt++)
#pragma unroll
        for (int nt = 0; nt < 8; nt++)
#pragma unroll
            for (int e = 0; e < 4; e++) acc[mt][nt][e] = 0.f;

    // async tile loader: A 256x32 (2048 16B-chunks), B 128x32 (1024 chunks)
    auto issue_tile = [&](int k0, int buf) {
        float* Ad = As + buf * GABUF;
        float* Bd = Bs + buf * GBBUF;
#pragma unroll
        for (int i = 0; i < 8; i++) {
            int c = tid + i * 256;
            int row = c >> 3, ch = (c & 7) * 4;
            cp16(&Ad[row * GSTR + ch], A + (size_t)(bm + row) * K + k0 + ch);
        }
#pragma unroll
        for (int i = 0; i < 4; i++) {
            int c = tid + i * 256;
            int row = c >> 3, ch = (c & 7) * 4;
            cp16(&Bd[row * GSTR + ch], Bm + (size_t)(bn + row) * K + k0 + ch);
        }
        CP_COMMIT();
    };

    issue_tile(0, 0);
    const int nit = K >> 5;
    for (int it = 0; it < nit; it++) {
        CP_WAIT0();
        __syncthreads();
        if (it + 1 < nit) issue_tile((it + 1) << 5, (it + 1) & 1);

        const float* Ac = As + (it & 1) * GABUF;
        const float* Bc = Bs + (it & 1) * GBBUF;
#pragma unroll
        for (int kc = 0; kc < 4; kc++) {
            const int ko = kc * 8;
            unsigned af[4][4];
#pragma unroll
            for (int mt = 0; mt < 4; mt++) {
                int r = wm + mt * 16 + qr;
                af[mt][0] = f2tf32(Ac[r * GSTR + ko + ql]);
                af[mt][1] = f2tf32(Ac[(r + 8) * GSTR + ko + ql]);
                af[mt][2] = f2tf32(Ac[r * GSTR + ko + ql + 4]);
                af[mt][3] = f2tf32(Ac[(r + 8) * GSTR + ko + ql + 4]);
            }
#pragma unroll
            for (int nt = 0; nt < 8; nt++) {
                int cb = wn + nt * 8 + qr;
                unsigned b0 = f2tf32(Bc[cb * GSTR + ko + ql]);
                unsigned b1 = f2tf32(Bc[cb * GSTR + ko + ql + 4]);
#pragma unroll
                for (int mt = 0; mt < 4; mt++)
                    mma_tf32(acc[mt][nt], af[mt][0], af[mt][1], af[mt][2], af[mt][3], b0, b1);
            }
        }
        __syncthreads();
    }

    // epilogue
#pragma unroll
    for (int mt = 0; mt < 4; mt++) {
        int r0 = bm + wm + mt * 16 + qr;
#pragma unroll
        for (int nt = 0; nt < 8; nt++) {
            int c0 = bn + wn + nt * 8 + ql * 2;
            float bz0 = bias ? bias[c0] : 0.f;
            float bz1 = bias ? bias[c0 + 1] : 0.f;
            float2 o0 = {acc[mt][nt][0] + bz0, acc[mt][nt][1] + bz1};
            float2 o1 = {acc[mt][nt][2] + bz0, acc[mt][nt][3] + bz1};
            *(float2*)(C + (size_t)r0 * N + c0) = o0;
            *(float2*)(C + (size_t)(r0 + 8) * N + c0) = o1;
        }
    }
}

// ---------------- Kernel 2/4: LN + RoPE, warp-per-head (no smem, no bar) ---------
__global__ void __launch_bounds__(512) ln_rope_kernel(const float* __restrict__ qkv,
                                                      const float* __restrict__ qg,
                                                      const float* __restrict__ qb,
                                                      const float* __restrict__ kg,
                                                      const float* __restrict__ kb) {
    const int m = blockIdx.x;              // b*S + s
    const int h = threadIdx.x >> 5;
    const int lane = threadIdx.x & 31;
    const int b = m / S;
    const int s = m % S;

    const float* row = qkv + (size_t)m * (3 * DIM) + h * HDIM;
    float q0 = row[lane],           q1 = row[lane + 32];
    float k0 = row[DIM + lane],     k1 = row[DIM + lane + 32];
    float v0 = row[2 * DIM + lane], v1 = row[2 * DIM + lane + 32];

    float sq = q0 + q1, sq2 = q0 * q0 + q1 * q1;
    float sk = k0 + k1, sk2 = k0 * k0 + k1 * k1;
#pragma unroll
    for (int o = 16; o; o >>= 1) {
        sq  += __shfl_xor_sync(0xffffffffu, sq, o);
        sq2 += __shfl_xor_sync(0xffffffffu, sq2, o);
        sk  += __shfl_xor_sync(0xffffffffu, sk, o);
        sk2 += __shfl_xor_sync(0xffffffffu, sk2, o);
    }
    float muq = sq * (1.f / HDIM);
    float rq = rsqrtf(sq2 * (1.f / HDIM) - muq * muq + EPS);
    float muk = sk * (1.f / HDIM);
    float rk = rsqrtf(sk2 * (1.f / HDIM) - muk * muk + EPS);

    float qn0 = (q0 - muq) * rq * qg[lane] + qb[lane];
    float qn1 = (q1 - muq) * rq * qg[lane + 32] + qb[lane + 32];
    float kn0 = (k0 - muk) * rk * kg[lane] + kb[lane];
    float kn1 = (k1 - muk) * rk * kg[lane + 32] + kb[lane + 32];

    float inv = powf(10000.f, -(float)lane * (1.f / 32.f));
    float c, sn;
    sincosf((float)s * inv, &sn, &c);
    float qo0 = (qn0 * c - qn1 * sn) * 0.125f;
    float qo1 = (qn1 * c + qn0 * sn) * 0.125f;
    float ko0 = kn0 * c - kn1 * sn;
    float ko1 = kn1 * c + kn0 * sn;

    const size_t idx = (((size_t)(b * NHEADS + h)) * S + s) * HDIM;
    g_q[idx + lane] = qo0;  g_q[idx + lane + 32] = qo1;
    g_k[idx + lane] = ko0;  g_k[idx + lane + 32] = ko1;
    g_v[idx + lane] = v0;   g_v[idx + lane + 32] = v1;
}

// ---------------- Kernel 3/4: flash attention, tf32, Q-frags in registers --------
#define AQ 128
#define AKT 64
#define ASTR 68
#define KVBUF (AKT * ASTR)
__global__ void __launch_bounds__(256) attn_tc(const float* __restrict__ Q,
                                               const float* __restrict__ K,
                                               const float* __restrict__ V,
                                               float* __restrict__ O) {
    extern __shared__ float sm[];
    float* Qs = sm;                       // [128][68] (reused as Ps after Q-frag hoist)
    float* Ks = Qs + AQ * ASTR;           // [2][64][68]  (key, dim)
    float* Vs = Ks + 2 * KVBUF;           // [2][64][68]  (dim, key) transposed
    float* Ps = Qs;                       // alias: Qs dead after fragment hoist

    const int bh = blockIdx.y;
    const int qt = blockIdx.x;
    const int b = bh / NHEADS;
    const int h = bh % NHEADS;

    const float* Qg = Q + ((size_t)bh * S + qt * AQ) * HDIM;
    const float* Kg = K + (size_t)bh * S * HDIM;
    const float* Vg = V + (size_t)bh * S * HDIM;

    const int tid = threadIdx.x;
    const int warp = tid >> 5;
    const int lane = tid & 31;
    const int wq = warp * 16;
    const int qr = lane >> 2;       // 0..7
    const int ql = lane & 3;        // 0..3
    const int lr = tid >> 4;        // 0..15 row group for loads
    const int lc4 = (tid & 15) * 4; // col*4 for loads

    // load Q tile (128x64), tf32 convert
#pragma unroll
    for (int i = 0; i < 8; i++) {
        int r = lr + i * 16;
        float4 q4 = *(const float4*)(Qg + r * HDIM + lc4);
        float* qp = &Qs[r * ASTR + lc4];
        qp[0] = f2tf32f(q4.x); qp[1] = f2tf32f(q4.y);
        qp[2] = f2tf32f(q4.z); qp[3] = f2tf32f(q4.w);
    }

    float ofrag[8][4];
#pragma unroll
    for (int dt = 0; dt < 8; dt++)
#pragma unroll
        for (int e = 0; e < 4; e++) ofrag[dt][e] = 0.f;
    float mrow0 = -CUDART_INF_F, mrow1 = -CUDART_INF_F;
    float lrow0 = 0.f, lrow1 = 0.f;

    float4 kr[4], vr[4];
    // prologue: load K/V tile 0 into regs, store into buffer 0
#pragma unroll
    for (int i = 0; i < 4; i++) {
        int r = lr + i * 16;
        kr[i] = *(const float4*)(Kg + r * HDIM + lc4);
        vr[i] = *(const float4*)(Vg + r * HDIM + lc4);
    }
#pragma unroll
    for (int i = 0; i < 4; i++) {
        int r = lr + i * 16;
        float* kp = &Ks[r * ASTR + lc4];
        kp[0] = f2tf32f(kr[i].x); kp[1] = f2tf32f(kr[i].y);
        kp[2] = f2tf32f(kr[i].z); kp[3] = f2tf32f(kr[i].w);
        Vs[(lc4 + 0) * ASTR + r] = f2tf32f(vr[i].x);
        Vs[(lc4 + 1) * ASTR + r] = f2tf32f(vr[i].y);
        Vs[(lc4 + 2) * ASTR + r] = f2tf32f(vr[i].z);
        Vs[(lc4 + 3) * ASTR + r] = f2tf32f(vr[i].w);
    }
    __syncthreads();

    // hoist Q fragments into registers (Qs smem becomes Ps after this)
    unsigned qfrag[8][4];
    {
        const int r = wq + qr;
#pragma unroll
        for (int kc = 0; kc < 8; kc++) {
            const int ko = kc * 8;
            qfrag[kc][0] = __float_as_uint(Qs[r * ASTR + ko + ql]);
            qfrag[kc][1] = __float_as_uint(Qs[(r + 8) * ASTR + ko + ql]);
            qfrag[kc][2] = __float_as_uint(Qs[r * ASTR + ko + ql + 4]);
            qfrag[kc][3] = __float_as_uint(Qs[(r + 8) * ASTR + ko + ql + 4]);
        }
    }
    // NOTE: no sync needed before Ps writes — each warp's Qs reads and Ps writes
    // cover the same disjoint 16-row band.

    const int nkt = S / AKT;
    for (int kt = 0; kt < nkt; kt++) {
        const int cur = kt & 1;
        if (kt + 1 < nkt) {
            const float* Kt = Kg + (size_t)(kt + 1) * AKT * HDIM;
            const float* Vt = Vg + (size_t)(kt + 1) * AKT * HDIM;
#pragma unroll
            for (int i = 0; i < 4; i++) {
                int r = lr + i * 16;
                kr[i] = *(const float4*)(Kt + r * HDIM + lc4);
                vr[i] = *(const float4*)(Vt + r * HDIM + lc4);
            }
        }
        const float* Kc = Ks + cur * KVBUF;
        const float* Vc = Vs + cur * KVBUF;

        // ---- scores: 16 x 64 per warp ----
        float sf[8][4];
#pragma unroll
        for (int nt = 0; nt < 8; nt++)
#pragma unroll
            for (int e = 0; e < 4; e++) sf[nt][e] = 0.f;

#pragma unroll
        for (int kc = 0; kc < 8; kc++) {
            const int ko = kc * 8;
#pragma unroll
            for (int nt = 0; nt < 8; nt++) {
                int cb = nt * 8 + qr;
                unsigned b0 = __float_as_uint(Kc[cb * ASTR + ko + ql]);
                unsigned b1 = __float_as_uint(Kc[cb * ASTR + ko + ql + 4]);
                mma_tf32(sf[nt], qfrag[kc][0], qfrag[kc][1], qfrag[kc][2], qfrag[kc][3], b0, b1);
            }
        }

        // ---- online softmax ----
        float mx0 = -CUDART_INF_F, mx1 = -CUDART_INF_F;
#pragma unroll
        for (int nt = 0; nt < 8; nt++) {
            mx0 = fmaxf(mx0, fmaxf(sf[nt][0], sf[nt][1]));
            mx1 = fmaxf(mx1, fmaxf(sf[nt][2], sf[nt][3]));
        }
        mx0 = fmaxf(mx0, __shfl_xor_sync(0xffffffffu, mx0, 1));
        mx0 = fmaxf(mx0, __shfl_xor_sync(0xffffffffu, mx0, 2));
        mx1 = fmaxf(mx1, __shfl_xor_sync(0xffffffffu, mx1, 1));
        mx1 = fmaxf(mx1, __shfl_xor_sync(0xffffffffu, mx1, 2));
        float nm0 = fmaxf(mrow0, mx0);
        float nm1 = fmaxf(mrow1, mx1);
        float corr0 = __expf(mrow0 - nm0);
        float corr1 = __expf(mrow1 - nm1);

        float sum0 = 0.f, sum1 = 0.f;
        const int r1 = wq + qr, r2 = r1 + 8;
#pragma unroll
        for (int nt = 0; nt < 8; nt++) {
            float p0 = __expf(sf[nt][0] - nm0);
            float p1 = __expf(sf[nt][1] - nm0);
            float p2 = __expf(sf[nt][2] - nm1);
            float p3 = __expf(sf[nt][3] - nm1);
            sum0 += p0 + p1;
            sum1 += p2 + p3;
            int c = nt * 8 + ql * 2;
            float2 s01 = {f2tf32f(p0), f2tf32f(p1)};
            float2 s23 = {f2tf32f(p2), f2tf32f(p3)};
            *(float2*)(&Ps[r1 * ASTR + c]) = s01;
            *(float2*)(&Ps[r2 * ASTR + c]) = s23;
        }
        sum0 += __shfl_xor_sync(0xffffffffu, sum0, 1);
        sum0 += __shfl_xor_sync(0xffffffffu, sum0, 2);
        sum1 += __shfl_xor_sync(0xffffffffu, sum1, 1);
        sum1 += __shfl_xor_sync(0xffffffffu, sum1, 2);
        lrow0 = lrow0 * corr0 + sum0;
        lrow1 = lrow1 * corr1 + sum1;
        mrow0 = nm0; mrow1 = nm1;
#pragma unroll
        for (int dt = 0; dt < 8; dt++) {
            ofrag[dt][0] *= corr0; ofrag[dt][1] *= corr0;
            ofrag[dt][2] *= corr1; ofrag[dt][3] *= corr1;
        }
        __syncwarp();

        // ---- PV: O[16 x 64] += P[16 x 64] @ V[64 x 64] ----
#pragma unroll
        for (int kc = 0; kc < 8; kc++) {
            const int ko = kc * 8;
            unsigned a0 = __float_as_uint(Ps[r1 * ASTR + ko + ql]);
            unsigned a1 = __float_as_uint(Ps[r2 * ASTR + ko + ql]);
            unsigned a2 = __float_as_uint(Ps[r1 * ASTR + ko + ql + 4]);
            unsigned a3 = __float_as_uint(Ps[r2 * ASTR + ko + ql + 4]);
#pragma unroll
            for (int dt = 0; dt < 8; dt++) {
                int db = dt * 8 + qr;
                unsigned b0 = __float_as_uint(Vc[db * ASTR + ko + ql]);
                unsigned b1 = __float_as_uint(Vc[db * ASTR + ko + ql + 4]);
                mma_tf32(ofrag[dt], a0, a1, a2, a3, b0, b1);
            }
        }

        // store prefetched tile into the other buffer
        if (kt + 1 < nkt) {
            const int nxt = (kt + 1) & 1;
            float* Kn = Ks + nxt * KVBUF;
            float* Vn = Vs + nxt * KVBUF;
#pragma unroll
            for (int i = 0; i < 4; i++) {
                int r = lr + i * 16;
                float* kp = &Kn[r * ASTR + lc4];
                kp[0] = f2tf32f(kr[i].x); kp[1] = f2tf32f(kr[i].y);
                kp[2] = f2tf32f(kr[i].z); kp[3] = f2tf32f(kr[i].w);
                Vn[(lc4 + 0) * ASTR + r] = f2tf32f(vr[i].x);
                Vn[(lc4 + 1) * ASTR + r] = f2tf32f(vr[i].y);
                Vn[(lc4 + 2) * ASTR + r] = f2tf32f(vr[i].z);
                Vn[(lc4 + 3) * ASTR + r] = f2tf32f(vr[i].w);
            }
        }
        __syncthreads();
    }

    // epilogue: write to [B,S,C] at column h*64
    const float inv0 = 1.f / lrow0;
    const float inv1 = 1.f / lrow1;
    const int r1g = qt * AQ + wq + qr;
#pragma unroll
    for (int dt = 0; dt < 8; dt++) {
        int c = dt * 8 + ql * 2;
        size_t o1 = ((size_t)b * S + r1g) * DIM + h * HDIM + c;
        size_t o2 = ((size_t)b * S + r1g + 8) * DIM + h * HDIM + c;
        float2 w1 = {ofrag[dt][0] * inv0, ofrag[dt][1] * inv0};
        float2 w2 = {ofrag[dt][2] * inv1, ofrag[dt][3] * inv1};
        *(float2*)(O + o1) = w1;
        *(float2*)(O + o2) = w2;
    }
}

// ---------------- launch ---------------------------------------------------------
extern "C" void kernel_launch(void* const* d_in, const int* in_sizes, int n_in,
                              void* d_out, int out_size) {
    const float* x      = (const float*)d_in[0];
    const float* w_qkv  = (const float*)d_in[1];
    const float* w_proj = (const float*)d_in[2];
    const float* b_proj = (const float*)d_in[3];
    const float* q_g    = (const float*)d_in[4];
    const float* q_b    = (const float*)d_in[5];
    const float* k_g    = (const float*)d_in[6];
    const float* k_b    = (const float*)d_in[7];
    float* out = (float*)d_out;

    float *p_qkv, *p_q, *p_k, *p_v, *p_o;
    cudaGetSymbolAddress((void**)&p_qkv, g_qkv);
    cudaGetSymbolAddress((void**)&p_q, g_q);
    cudaGetSymbolAddress((void**)&p_k, g_k);
    cudaGetSymbolAddress((void**)&p_v, g_v);
    cudaGetSymbolAddress((void**)&p_o, g_o);

    const int gemm_smem = (2 * GABUF + 2 * GBBUF) * sizeof(float);  // ~110 KB
    cudaFuncSetAttribute(gemm_tf32, cudaFuncAttributeMaxDynamicSharedMemorySize, gemm_smem);

    // 1) QKV projection: [4096,3072] = x @ w_qkv^T
    gemm_tf32<<<dim3(3 * DIM / 128, M_TOT / 256), 256, gemm_smem>>>(
        x, w_qkv, nullptr, p_qkv, M_TOT, 3 * DIM, DIM);

    // 2) LN + RoPE + scale + transpose to [B,H,S,D]
    ln_rope_kernel<<<M_TOT, 512>>>(p_qkv, q_g, q_b, k_g, k_b);

    // 3) flash attention (tensor core, Q frags in regs, double-buffered K/V)
    const int attn_smem = (AQ * ASTR + 4 * KVBUF) * sizeof(float);  // ~104 KB
    cudaFuncSetAttribute(attn_tc, cudaFuncAttributeMaxDynamicSharedMemorySize, attn_smem);
    attn_tc<<<dim3(S / AQ, B * NHEADS), 256, attn_smem>>>(p_q, p_k, p_v, p_o);

    // 4) output projection: out = O @ w_proj^T + b_proj
    gemm_tf32<<<dim3(DIM / 128, M_TOT / 256), 256, gemm_smem>>>(
        p_o, w_proj, b_proj, out, M_TOT, DIM, DIM);
}